// round 1
// baseline (speedup 1.0000x reference)
#include <cuda_runtime.h>
#include <cstdint>

// Problem: B=4096, K=64, DIM=512, obj=0 path:
//   out = sum_{b, k != labels[b]} exp( -||inputs[b,:] - decoded[b,k,:]||^2 )
// Inputs (metadata order): inputs f32[B*DIM], decoded f32[B*K*DIM],
//                          labels int64[B], obj (scalar int, ==0 here)
// Output: single f32 scalar.

#define B_   4096
#define K_   64
#define DIM_ 512

__global__ void zero_out_kernel(float* out) {
    if (threadIdx.x == 0) out[0] = 0.0f;
}

// One CTA per batch row. 256 threads = 8 warps; each warp handles 8 k-rows.
// inputs[b] staged in shared (2KB). Each lane loads 4x float4 per row
// (512 floats / 32 lanes = 16 floats = 4 float4), giving MLP=4 coalesced
// 128B-line streams per warp-row.
__global__ __launch_bounds__(256, 8)
void mse_exp_loss_kernel(const float* __restrict__ inputs,
                         const float* __restrict__ decoded,
                         const long long* __restrict__ labels,
                         float* __restrict__ out) {
    __shared__ float4 s_in[DIM_ / 4];   // 128 float4 = 512 floats = 2KB

    const int b = blockIdx.x;

    // Stage inputs[b]
    const float4* inrow = reinterpret_cast<const float4*>(inputs + (size_t)b * DIM_);
    for (int i = threadIdx.x; i < DIM_ / 4; i += blockDim.x)
        s_in[i] = inrow[i];
    __syncthreads();

    const int warp = threadIdx.x >> 5;
    const int lane = threadIdx.x & 31;
    const int lbl  = (int)labels[b];

    float acc = 0.0f;

    #pragma unroll
    for (int kk = 0; kk < K_ / 8; kk++) {
        const int k = warp * 8 + kk;
        const float4* drow = reinterpret_cast<const float4*>(
            decoded + ((size_t)b * K_ + k) * DIM_);

        float s = 0.0f;
        #pragma unroll
        for (int i = 0; i < 4; i++) {
            // streaming hint: decoded has zero reuse, keep it out of L2's way
            const float4 d = __ldcs(&drow[lane + i * 32]);
            const float4 x = s_in[lane + i * 32];
            const float e0 = x.x - d.x;
            const float e1 = x.y - d.y;
            const float e2 = x.z - d.z;
            const float e3 = x.w - d.w;
            s = fmaf(e0, e0, s);
            s = fmaf(e1, e1, s);
            s = fmaf(e2, e2, s);
            s = fmaf(e3, e3, s);
        }

        // warp tree-reduce the 512-element squared distance
        #pragma unroll
        for (int o = 16; o > 0; o >>= 1)
            s += __shfl_xor_sync(0xFFFFFFFFu, s, o);

        if (lane == 0 && k != lbl)
            acc += __expf(-s);   // underflows to 0 for large s, matching fp32 ref
    }

    if (lane == 0)
        atomicAdd(out, acc);
}

extern "C" void kernel_launch(void* const* d_in, const int* in_sizes, int n_in,
                              void* d_out, int out_size) {
    const float*     inputs  = (const float*)d_in[0];
    const float*     decoded = (const float*)d_in[1];
    const long long* labels  = (const long long*)d_in[2];
    float* out = (float*)d_out;

    zero_out_kernel<<<1, 32>>>(out);
    mse_exp_loss_kernel<<<B_, 256>>>(inputs, decoded, labels, out);
}